// round 5
// baseline (speedup 1.0000x reference)
#include <cuda_runtime.h>
#include <cuda_bf16.h>
#include <cstdint>

#define BATCH   64
#define TSTEPS  128
#define TB      8192
#define DIN     768
#define H1      512
#define G1N     2048
#define H2      256
#define G2N     1024

// ---------------- static device scratch (no allocations) ----------------
__device__ float g_G1[(size_t)TB * G1N];   // 64 MB: x @ W_ih1^T + b_ih1 + b_hh1
__device__ float g_G2[(size_t)TB * G2N];   // 32 MB: hs1 @ W_ih2^T + b_ih2 + b_hh2
__device__ float g_hs1[(size_t)TB * H1];   // 16 MB: LSTM1 outputs, row r = t*64+b
__device__ float g_hT[2][H1 * BATCH];      // h1 transposed [j][b], double-buffered by parity
__device__ float g_c1[BATCH * H1];         // LSTM1 cell state [b][j]
__device__ float g_hT2[H2];                // final LSTM2 hidden

__device__ __forceinline__ float sigf(float x) { return 1.0f / (1.0f + __expf(-x)); }

// ---------------- zero init ----------------
__global__ void zero_state() {
    int id = blockIdx.x * blockDim.x + threadIdx.x;   // 32768 threads
    g_c1[id] = 0.0f;
    g_hT[0][id] = 0.0f;
}

// ---------------- GEMM: C[M,N] = A[M,K] @ B[N,K]^T + bias1 + bias2 ----------------
// MODE 0: A = x with (t,b)->row permutation, C = g_G1, N=2048, K=768
// MODE 1: A = g_hs1 linear,                  C = g_G2, N=1024, K=512
template <int MODE>
__global__ void __launch_bounds__(256) gemm64(const float* __restrict__ A,
                                              const float* __restrict__ B,
                                              const float* __restrict__ bias1,
                                              const float* __restrict__ bias2) {
    constexpr int N = (MODE == 0) ? G1N : G2N;
    constexpr int K = (MODE == 0) ? DIN : H1;
    float* __restrict__ C = (MODE == 0) ? g_G1 : g_G2;
    const float* __restrict__ Ap = (MODE == 0) ? A : g_hs1;

    __shared__ float As[16][64];
    __shared__ float Bs[16][64];

    int tid = threadIdx.x;
    int m0 = blockIdx.y * 64, n0 = blockIdx.x * 64;
    int tx = tid & 15, ty = tid >> 4;

    int la_m = tid & 63, la_k = (tid >> 6) * 4;   // A loader: 64 rows x 4 k
    int lb_n = tid >> 2, lb_k = (tid & 3) * 4;    // B loader: 64 rows x 4 k

    int r = m0 + la_m;
    size_t arow;
    if (MODE == 0) {
        int b = r & 63, t = r >> 6;               // r = t*64 + b
        arow = ((size_t)b * TSTEPS + t) * DIN;    // x[b, t, :]
    } else {
        arow = (size_t)r * K;
    }

    float acc[4][4];
#pragma unroll
    for (int i = 0; i < 4; i++)
#pragma unroll
        for (int j = 0; j < 4; j++) acc[i][j] = 0.0f;

    for (int kt = 0; kt < K; kt += 16) {
        float4 av = *(const float4*)(Ap + arow + kt + la_k);
        As[la_k + 0][la_m] = av.x;
        As[la_k + 1][la_m] = av.y;
        As[la_k + 2][la_m] = av.z;
        As[la_k + 3][la_m] = av.w;
        float4 bv = *(const float4*)(B + (size_t)(n0 + lb_n) * K + kt + lb_k);
        Bs[lb_k + 0][lb_n] = bv.x;
        Bs[lb_k + 1][lb_n] = bv.y;
        Bs[lb_k + 2][lb_n] = bv.z;
        Bs[lb_k + 3][lb_n] = bv.w;
        __syncthreads();
#pragma unroll
        for (int k = 0; k < 16; k++) {
            float4 a  = ((const float4*)As[k])[ty];
            float4 b4 = ((const float4*)Bs[k])[tx];
            acc[0][0] = fmaf(a.x, b4.x, acc[0][0]);
            acc[0][1] = fmaf(a.x, b4.y, acc[0][1]);
            acc[0][2] = fmaf(a.x, b4.z, acc[0][2]);
            acc[0][3] = fmaf(a.x, b4.w, acc[0][3]);
            acc[1][0] = fmaf(a.y, b4.x, acc[1][0]);
            acc[1][1] = fmaf(a.y, b4.y, acc[1][1]);
            acc[1][2] = fmaf(a.y, b4.z, acc[1][2]);
            acc[1][3] = fmaf(a.y, b4.w, acc[1][3]);
            acc[2][0] = fmaf(a.z, b4.x, acc[2][0]);
            acc[2][1] = fmaf(a.z, b4.y, acc[2][1]);
            acc[2][2] = fmaf(a.z, b4.z, acc[2][2]);
            acc[2][3] = fmaf(a.z, b4.w, acc[2][3]);
            acc[3][0] = fmaf(a.w, b4.x, acc[3][0]);
            acc[3][1] = fmaf(a.w, b4.y, acc[3][1]);
            acc[3][2] = fmaf(a.w, b4.z, acc[3][2]);
            acc[3][3] = fmaf(a.w, b4.w, acc[3][3]);
        }
        __syncthreads();
    }

    int coln = n0 + tx * 4;
    float bb0 = bias1[coln + 0] + bias2[coln + 0];
    float bb1 = bias1[coln + 1] + bias2[coln + 1];
    float bb2 = bias1[coln + 2] + bias2[coln + 2];
    float bb3 = bias1[coln + 3] + bias2[coln + 3];
#pragma unroll
    for (int i = 0; i < 4; i++) {
        int row = m0 + ty * 4 + i;
        float4 o;
        o.x = acc[i][0] + bb0;
        o.y = acc[i][1] + bb1;
        o.z = acc[i][2] + bb2;
        o.w = acc[i][3] + bb3;
        *(float4*)(C + (size_t)row * N + coln) = o;
    }
}

// ---------------- LSTM1 fused step: 128 blocks x 256 threads, 4 hidden units/block ------------
__global__ void __launch_bounds__(256) lstm1_step(const float* __restrict__ Whh1, int t) {
    __shared__ float Hs[64 * 64];   // [k][b]
    __shared__ float Ws[64 * 16];   // [k][c]
    __shared__ float sg[16 * 64];   // [c][b]

    int tid = threadIdx.x;
    int j0 = blockIdx.x * 4;
    int c  = tid & 15;     // local gate column 0..15
    int bg = tid >> 4;     // batch group 0..15 (4 batches each)
    int gg_ = c >> 2, u = c & 3;
    int gcol = gg_ * H1 + j0 + u;
    int rp = t & 1;        // read parity

    const float* hsrc = g_hT[rp];

    float a0 = 0.f, a1 = 0.f, a2 = 0.f, a3 = 0.f;
    for (int kt = 0; kt < H1; kt += 64) {
        const float4* src = (const float4*)(hsrc + kt * 64);
        float4* dst = (float4*)Hs;
#pragma unroll
        for (int i = 0; i < 4; i++) dst[tid + i * 256] = src[tid + i * 256];
        {
            int wc = tid & 15, wk4 = tid >> 4;
            int wg = wc >> 2, wu = wc & 3;
            float4 wv = *(const float4*)(Whh1 + (size_t)(wg * H1 + j0 + wu) * H1 + kt + wk4 * 4);
            Ws[(wk4 * 4 + 0) * 16 + wc] = wv.x;
            Ws[(wk4 * 4 + 1) * 16 + wc] = wv.y;
            Ws[(wk4 * 4 + 2) * 16 + wc] = wv.z;
            Ws[(wk4 * 4 + 3) * 16 + wc] = wv.w;
        }
        __syncthreads();
#pragma unroll 16
        for (int k = 0; k < 64; k++) {
            float4 h4 = ((const float4*)(Hs + k * 64))[bg];
            float w = Ws[k * 16 + c];
            a0 = fmaf(h4.x, w, a0);
            a1 = fmaf(h4.y, w, a1);
            a2 = fmaf(h4.z, w, a2);
            a3 = fmaf(h4.w, w, a3);
        }
        __syncthreads();
    }

    int b0 = bg * 4;
    size_t gbase = ((size_t)(t * BATCH + b0)) * G1N + gcol;
    sg[c * 64 + b0 + 0] = a0 + g_G1[gbase];
    sg[c * 64 + b0 + 1] = a1 + g_G1[gbase + G1N];
    sg[c * 64 + b0 + 2] = a2 + g_G1[gbase + 2 * (size_t)G1N];
    sg[c * 64 + b0 + 3] = a3 + g_G1[gbase + 3 * (size_t)G1N];
    __syncthreads();

    // pointwise: 256 threads = 4 units x 64 batches
    int u2 = tid >> 6, b = tid & 63;
    float gi = sigf(sg[(0 * 4 + u2) * 64 + b]);
    float gf = sigf(sg[(1 * 4 + u2) * 64 + b]);
    float gc = tanhf(sg[(2 * 4 + u2) * 64 + b]);
    float go = sigf(sg[(3 * 4 + u2) * 64 + b]);
    int jj = j0 + u2;
    int ci = b * H1 + jj;
    float cc = fmaf(gf, g_c1[ci], gi * gc);
    g_c1[ci] = cc;
    float h = go * tanhf(cc);
    g_hT[rp ^ 1][jj * BATCH + b] = h;
    g_hs1[((size_t)(t * BATCH + b)) * H1 + jj] = h;
}

// ---------------- LSTM2: 8192 serial steps, cluster of 8, weights register-resident ------------
__global__ void __cluster_dims__(8, 1, 1) __launch_bounds__(512, 1)
lstm2_kernel(const float* __restrict__ Whh2) {
    __shared__ __align__(16) float sh_h[2][H2];
    __shared__ float sg2[128];

    int tid = threadIdx.x;
    uint32_t rank;
    asm("mov.u32 %0, %%cluster_ctarank;" : "=r"(rank));

    int lr = tid >> 2;   // local gate row 0..127
    int kq = tid & 3;    // k quarter
    int g  = lr >> 5;    // gate 0=i 1=f 2=g 3=o
    int j  = lr & 31;    // unit within this CTA's 32-unit slice
    int gr = g * H2 + (int)rank * 32 + j;

    // W_hh2 row slice resident in registers for the whole scan
    float w[64];
    const float4* wp = (const float4*)(Whh2 + (size_t)gr * H2 + kq * 64);
#pragma unroll
    for (int i = 0; i < 16; i++) {
        float4 v = wp[i];
        w[4 * i + 0] = v.x; w[4 * i + 1] = v.y; w[4 * i + 2] = v.z; w[4 * i + 3] = v.w;
    }

    if (tid < H2) sh_h[0][tid] = 0.0f;
    float c = 0.0f;
    float u_next = (kq == 0) ? __ldg(&g_G2[gr]) : 0.0f;

    // Pre-resolve DSMEM addresses of both h buffers in all 8 peer CTAs (hoisted mapa)
    uint32_t hb0 = (uint32_t)__cvta_generic_to_shared(&sh_h[0][0]);
    uint32_t peer0[8], peer1[8];
    if (tid < 32) {
        uint32_t l0 = hb0 + (uint32_t)((int)rank * 32 + tid) * 4u;
        uint32_t l1 = l0 + H2 * 4u;
#pragma unroll
        for (int dst = 0; dst < 8; dst++) {
            asm("mapa.shared::cluster.u32 %0, %1, %2;" : "=r"(peer0[dst]) : "r"(l0), "r"(dst));
            asm("mapa.shared::cluster.u32 %0, %1, %2;" : "=r"(peer1[dst]) : "r"(l1), "r"(dst));
        }
    }

    asm volatile("barrier.cluster.arrive.aligned;" ::: "memory");
    asm volatile("barrier.cluster.wait.aligned;" ::: "memory");

    int buf = 0;
    for (int r = 0; r < TB; r++) {
        float u = u_next;
        if (kq == 0 && r + 1 < TB) u_next = __ldg(&g_G2[(size_t)(r + 1) * G2N + gr]);

        const float* hbp = &sh_h[buf][kq * 64];
        float a0 = 0.f, a1 = 0.f, a2 = 0.f, a3 = 0.f;
#pragma unroll
        for (int i = 0; i < 16; i++) {
            float4 h4 = *(const float4*)(hbp + 4 * i);
            a0 = fmaf(w[4 * i + 0], h4.x, a0);
            a1 = fmaf(w[4 * i + 1], h4.y, a1);
            a2 = fmaf(w[4 * i + 2], h4.z, a2);
            a3 = fmaf(w[4 * i + 3], h4.w, a3);
        }
        float acc = (a0 + a1) + (a2 + a3);
        acc += __shfl_xor_sync(0xffffffffu, acc, 1);
        acc += __shfl_xor_sync(0xffffffffu, acc, 2);

        if (kq == 0) {
            float pre = acc + u;
            sg2[lr] = (g == 2) ? tanhf(pre) : sigf(pre);
        }
        __syncthreads();

        int nb = buf ^ 1;
        if (tid < 32) {
            float gi = sg2[tid];
            float gf = sg2[32 + tid];
            float gc = sg2[64 + tid];
            float go = sg2[96 + tid];
            c = fmaf(gf, c, gi * gc);
            float h = go * tanhf(c);
            uint32_t hv = __float_as_uint(h);
            if (nb == 0) {
#pragma unroll
                for (int dst = 0; dst < 8; dst++)
                    asm volatile("st.shared::cluster.u32 [%0], %1;" :: "r"(peer0[dst]), "r"(hv) : "memory");
            } else {
#pragma unroll
                for (int dst = 0; dst < 8; dst++)
                    asm volatile("st.shared::cluster.u32 [%0], %1;" :: "r"(peer1[dst]), "r"(hv) : "memory");
            }
        }
        // release-arrive orders the DSMEM h stores; acquire-wait makes them visible cluster-wide
        asm volatile("barrier.cluster.arrive.aligned;" ::: "memory");
        asm volatile("barrier.cluster.wait.aligned;" ::: "memory");
        buf = nb;
    }

    if (rank == 0 && tid < H2) g_hT2[tid] = sh_h[buf][tid];
}

// ---------------- tail MLP ----------------
__global__ void mlp_kernel(const float* __restrict__ W1, const float* __restrict__ b1,
                           const float* __restrict__ W2, const float* __restrict__ b2,
                           float* __restrict__ out) {
    __shared__ float emb[H2];
    __shared__ float o1[128];
    int tid = threadIdx.x;  // 128
    {
        float h0 = g_hT2[tid];
        float h1 = g_hT2[tid + 128];
        emb[tid]       = h0 + h0 * h0;
        emb[tid + 128] = h1 + h1 * h1;
    }
    __syncthreads();
    float s = b1[tid];
    const float* wrow = W1 + (size_t)tid * H2;
#pragma unroll 8
    for (int k = 0; k < H2; k++) s = fmaf(emb[k], wrow[k], s);
    o1[tid] = s;
    __syncthreads();
    if (tid < 10) {
        float s2 = b2[tid];
        const float* w2r = W2 + (size_t)tid * 128;
#pragma unroll 8
        for (int k = 0; k < 128; k++) s2 = fmaf(o1[k], w2r[k], s2);
        out[tid] = s2;
    }
}

extern "C" void kernel_launch(void* const* d_in, const int* in_sizes, int n_in,
                              void* d_out, int out_size) {
    const float* x     = (const float*)d_in[0];
    const float* W_ih1 = (const float*)d_in[1];
    const float* W_hh1 = (const float*)d_in[2];
    const float* b_ih1 = (const float*)d_in[3];
    const float* b_hh1 = (const float*)d_in[4];
    const float* W_ih2 = (const float*)d_in[5];
    const float* W_hh2 = (const float*)d_in[6];
    const float* b_ih2 = (const float*)d_in[7];
    const float* b_hh2 = (const float*)d_in[8];
    const float* W1    = (const float*)d_in[9];
    const float* b1    = (const float*)d_in[10];
    const float* W2    = (const float*)d_in[11];
    const float* b2    = (const float*)d_in[12];
    float* out = (float*)d_out;

    zero_state<<<128, 256>>>();

    // G1 = x(permuted) @ W_ih1^T + b_ih1 + b_hh1   [8192 x 2048]
    gemm64<0><<<dim3(G1N / 64, TB / 64), 256>>>(x, W_ih1, b_ih1, b_hh1);

    // LSTM1: 128 serial fused steps
    for (int t = 0; t < TSTEPS; t++) {
        lstm1_step<<<128, 256>>>(W_hh1, t);
    }

    // G2 = hs1 @ W_ih2^T + b_ih2 + b_hh2   [8192 x 1024]
    gemm64<1><<<dim3(G2N / 64, TB / 64), 256>>>(x, W_ih2, b_ih2, b_hh2);

    // LSTM2: one persistent cluster kernel over 8192 serial steps
    lstm2_kernel<<<8, 512>>>(W_hh2);

    // tail MLP -> out[10]
    mlp_kernel<<<1, 128>>>(W1, b1, W2, b2, out);
}

// round 7
// speedup vs baseline: 1.4827x; 1.4827x over previous
#include <cuda_runtime.h>
#include <cuda_bf16.h>
#include <cstdint>

#define BATCH   64
#define TSTEPS  128
#define TB      8192
#define DIN     768
#define H1      512
#define G1N     2048
#define H2      256
#define G2N     1024

// ---------------- static device scratch (no allocations) ----------------
__device__ float g_G1[(size_t)TB * G1N];   // 64 MB
__device__ float g_G2[(size_t)TB * G2N];   // 32 MB
__device__ float g_hs1[(size_t)TB * H1];   // 16 MB
__device__ float g_hT[2][H1 * BATCH];      // h1 transposed [j][b], double-buffered
__device__ float g_c1[BATCH * H1];         // LSTM1 cell state [b][j]
__device__ float g_hT2[H2];                // final LSTM2 hidden

__device__ __forceinline__ float sigf(float x) { return 1.0f / (1.0f + __expf(-x)); }

__global__ void zero_state() {
    int id = blockIdx.x * blockDim.x + threadIdx.x;   // 32768 threads
    g_c1[id] = 0.0f;
    g_hT[0][id] = 0.0f;
}

// ---------------- GEMM: C[M,N] = A[M,K] @ B[N,K]^T + bias1 + bias2 ----------------
template <int MODE>
__global__ void __launch_bounds__(256) gemm64(const float* __restrict__ A,
                                              const float* __restrict__ B,
                                              const float* __restrict__ bias1,
                                              const float* __restrict__ bias2) {
    constexpr int N = (MODE == 0) ? G1N : G2N;
    constexpr int K = (MODE == 0) ? DIN : H1;
    float* __restrict__ C = (MODE == 0) ? g_G1 : g_G2;
    const float* __restrict__ Ap = (MODE == 0) ? A : g_hs1;

    __shared__ float As[16][64];
    __shared__ float Bs[16][64];

    int tid = threadIdx.x;
    int m0 = blockIdx.y * 64, n0 = blockIdx.x * 64;
    int tx = tid & 15, ty = tid >> 4;

    int la_m = tid & 63, la_k = (tid >> 6) * 4;
    int lb_n = tid >> 2, lb_k = (tid & 3) * 4;

    int r = m0 + la_m;
    size_t arow;
    if (MODE == 0) {
        int b = r & 63, t = r >> 6;
        arow = ((size_t)b * TSTEPS + t) * DIN;
    } else {
        arow = (size_t)r * K;
    }

    float acc[4][4];
#pragma unroll
    for (int i = 0; i < 4; i++)
#pragma unroll
        for (int j = 0; j < 4; j++) acc[i][j] = 0.0f;

    for (int kt = 0; kt < K; kt += 16) {
        float4 av = *(const float4*)(Ap + arow + kt + la_k);
        As[la_k + 0][la_m] = av.x;
        As[la_k + 1][la_m] = av.y;
        As[la_k + 2][la_m] = av.z;
        As[la_k + 3][la_m] = av.w;
        float4 bv = *(const float4*)(B + (size_t)(n0 + lb_n) * K + kt + lb_k);
        Bs[lb_k + 0][lb_n] = bv.x;
        Bs[lb_k + 1][lb_n] = bv.y;
        Bs[lb_k + 2][lb_n] = bv.z;
        Bs[lb_k + 3][lb_n] = bv.w;
        __syncthreads();
#pragma unroll
        for (int k = 0; k < 16; k++) {
            float4 a  = ((const float4*)As[k])[ty];
            float4 b4 = ((const float4*)Bs[k])[tx];
            acc[0][0] = fmaf(a.x, b4.x, acc[0][0]);
            acc[0][1] = fmaf(a.x, b4.y, acc[0][1]);
            acc[0][2] = fmaf(a.x, b4.z, acc[0][2]);
            acc[0][3] = fmaf(a.x, b4.w, acc[0][3]);
            acc[1][0] = fmaf(a.y, b4.x, acc[1][0]);
            acc[1][1] = fmaf(a.y, b4.y, acc[1][1]);
            acc[1][2] = fmaf(a.y, b4.z, acc[1][2]);
            acc[1][3] = fmaf(a.y, b4.w, acc[1][3]);
            acc[2][0] = fmaf(a.z, b4.x, acc[2][0]);
            acc[2][1] = fmaf(a.z, b4.y, acc[2][1]);
            acc[2][2] = fmaf(a.z, b4.z, acc[2][2]);
            acc[2][3] = fmaf(a.z, b4.w, acc[2][3]);
            acc[3][0] = fmaf(a.w, b4.x, acc[3][0]);
            acc[3][1] = fmaf(a.w, b4.y, acc[3][1]);
            acc[3][2] = fmaf(a.w, b4.z, acc[3][2]);
            acc[3][3] = fmaf(a.w, b4.w, acc[3][3]);
        }
        __syncthreads();
    }

    int coln = n0 + tx * 4;
    float bb0 = bias1[coln + 0] + bias2[coln + 0];
    float bb1 = bias1[coln + 1] + bias2[coln + 1];
    float bb2 = bias1[coln + 2] + bias2[coln + 2];
    float bb3 = bias1[coln + 3] + bias2[coln + 3];
#pragma unroll
    for (int i = 0; i < 4; i++) {
        int row = m0 + ty * 4 + i;
        float4 o;
        o.x = acc[i][0] + bb0;
        o.y = acc[i][1] + bb1;
        o.z = acc[i][2] + bb2;
        o.w = acc[i][3] + bb3;
        *(float4*)(C + (size_t)row * N + coln) = o;
    }
}

// ---------------- LSTM1 fused step: 128 blocks x 512 threads, 2-way K split ----------------
__global__ void __launch_bounds__(512) lstm1_step(const float* __restrict__ Whh1, int t) {
    __shared__ float Hs[2][64 * 64];   // 32 KB : per-half [k][b] tiles
    __shared__ float Ws[2][64 * 16];   // 8 KB  : per-half [k][c] tiles
    __shared__ float sg[16 * 64];      // 4 KB  : [c][b] gate pre-activations

    int tid = threadIdx.x;
    int half = tid >> 8;       // 0/1: k-range half (k in [half*256, half*256+256))
    int lt = tid & 255;
    int c  = lt & 15;          // local gate column 0..15
    int bg = lt >> 4;          // batch group 0..15
    int j0 = blockIdx.x * 4;
    int gg_ = c >> 2, u = c & 3;
    int rp = t & 1;
    const float* hsrc = g_hT[rp];

    float a0 = 0.f, a1 = 0.f, a2 = 0.f, a3 = 0.f;
#pragma unroll
    for (int kk = 0; kk < 4; kk++) {               // FIX: 4 tiles of 64 => full 256-k half
        int kt = half * 256 + kk * 64;
        const float4* src = (const float4*)(hsrc + kt * 64);
        float4* dst = (float4*)Hs[half];
#pragma unroll
        for (int i = 0; i < 4; i++) dst[lt + i * 256] = src[lt + i * 256];
        {
            int wc = lt & 15, wk4 = lt >> 4;
            int wg = wc >> 2, wu = wc & 3;
            float4 wv = *(const float4*)(Whh1 + (size_t)(wg * H1 + j0 + wu) * H1 + kt + wk4 * 4);
            float* W = Ws[half];
            W[(wk4 * 4 + 0) * 16 + wc] = wv.x;
            W[(wk4 * 4 + 1) * 16 + wc] = wv.y;
            W[(wk4 * 4 + 2) * 16 + wc] = wv.z;
            W[(wk4 * 4 + 3) * 16 + wc] = wv.w;
        }
        __syncthreads();
        const float* HH = Hs[half];
        const float* WW = Ws[half];
#pragma unroll 16
        for (int k = 0; k < 64; k++) {
            float4 h4 = ((const float4*)(HH + k * 64))[bg];
            float w = WW[k * 16 + c];
            a0 = fmaf(h4.x, w, a0);
            a1 = fmaf(h4.y, w, a1);
            a2 = fmaf(h4.z, w, a2);
            a3 = fmaf(h4.w, w, a3);
        }
        __syncthreads();
    }

    int b0 = bg * 4;
    int gcol = gg_ * H1 + j0 + u;
    if (half == 0) {
        size_t gbase = ((size_t)(t * BATCH + b0)) * G1N + gcol;
        sg[c * 64 + b0 + 0] = a0 + g_G1[gbase];
        sg[c * 64 + b0 + 1] = a1 + g_G1[gbase + G1N];
        sg[c * 64 + b0 + 2] = a2 + g_G1[gbase + 2 * (size_t)G1N];
        sg[c * 64 + b0 + 3] = a3 + g_G1[gbase + 3 * (size_t)G1N];
    }
    __syncthreads();
    if (half == 1) {
        sg[c * 64 + b0 + 0] += a0;
        sg[c * 64 + b0 + 1] += a1;
        sg[c * 64 + b0 + 2] += a2;
        sg[c * 64 + b0 + 3] += a3;
    }
    __syncthreads();

    if (tid < 256) {
        int u2 = tid >> 6, b = tid & 63;
        float gi = sigf(sg[(0 * 4 + u2) * 64 + b]);
        float gf = sigf(sg[(1 * 4 + u2) * 64 + b]);
        float gc = tanhf(sg[(2 * 4 + u2) * 64 + b]);
        float go = sigf(sg[(3 * 4 + u2) * 64 + b]);
        int jj = j0 + u2;
        int ci = b * H1 + jj;
        float cc = fmaf(gf, g_c1[ci], gi * gc);
        g_c1[ci] = cc;
        float h = go * tanhf(cc);
        g_hT[rp ^ 1][jj * BATCH + b] = h;
        g_hs1[((size_t)(t * BATCH + b)) * H1 + jj] = h;
    }
}

// ---------------- LSTM2: cluster of 8, per-source mbarrier handshake, f32x2 FMA ------------
__device__ __forceinline__ void mbar_wait_cluster(uint32_t mbar, uint32_t parity) {
    asm volatile(
        "{\n\t"
        ".reg .pred P;\n\t"
        "WAIT_%=:\n\t"
        "mbarrier.try_wait.parity.acquire.cluster.shared::cta.b64 P, [%0], %1, 0x989680;\n\t"
        "@P bra.uni DONE_%=;\n\t"
        "bra.uni WAIT_%=;\n\t"
        "DONE_%=:\n\t"
        "}" :: "r"(mbar), "r"(parity) : "memory");
}

__global__ void __cluster_dims__(8, 1, 1) __launch_bounds__(512, 1)
lstm2_kernel(const float* __restrict__ Whh2) {
    __shared__ __align__(16) float sh_h[2][H2];
    __shared__ float sg2[128];
    __shared__ __align__(8) unsigned long long mb[2][8];   // [buf][src CTA]

    int tid = threadIdx.x;
    uint32_t rank;
    asm("mov.u32 %0, %%cluster_ctarank;" : "=r"(rank));

    int lr = tid >> 2;   // gate row 0..127
    int kq = tid & 3;    // k quarter
    int g  = lr >> 5;    // gate 0=i 1=f 2=g 3=o
    int j  = lr & 31;
    int gr = g * H2 + (int)rank * 32 + j;

    // W row slice, pre-packed as f32x2 pairs
    unsigned long long w2[32];
    {
        const ulonglong2* wp = (const ulonglong2*)(Whh2 + (size_t)gr * H2 + kq * 64);
#pragma unroll
        for (int i = 0; i < 16; i++) {
            ulonglong2 v = wp[i];
            w2[2 * i] = v.x; w2[2 * i + 1] = v.y;
        }
    }

    if (tid < H2) sh_h[0][tid] = 0.0f;

    uint32_t mbb = (uint32_t)__cvta_generic_to_shared(&mb[0][0]);
    if (tid < 16) {
        uint32_t a = mbb + tid * 8u;
        asm volatile("mbarrier.init.shared.b64 [%0], %1;" :: "r"(a), "r"(4) : "memory");
    }
    __syncthreads();
    asm volatile("barrier.cluster.arrive.aligned;" ::: "memory");
    asm volatile("barrier.cluster.wait.aligned;" ::: "memory");

    // writer-lane precomputed remote addresses (lane -> one peer d, 8-float slot q)
    uint32_t rh[2], rm[2];
    uint32_t hb = (uint32_t)__cvta_generic_to_shared(&sh_h[0][0]);
    if (tid < 32) {
        int d = tid >> 2, q = tid & 3;
        uint32_t l0 = hb + (uint32_t)((int)rank * 32 + q * 8) * 4u;       // buf0 slot
        uint32_t l1 = l0 + H2 * 4u;                                       // buf1 slot
        uint32_t m0 = mbb + (uint32_t)(0 * 8 + (int)rank) * 8u;           // mb[0][rank]
        uint32_t m1 = mbb + (uint32_t)(1 * 8 + (int)rank) * 8u;           // mb[1][rank]
        asm("mapa.shared::cluster.u32 %0, %1, %2;" : "=r"(rh[0]) : "r"(l0), "r"(d));
        asm("mapa.shared::cluster.u32 %0, %1, %2;" : "=r"(rh[1]) : "r"(l1), "r"(d));
        asm("mapa.shared::cluster.u32 %0, %1, %2;" : "=r"(rm[0]) : "r"(m0), "r"(d));
        asm("mapa.shared::cluster.u32 %0, %1, %2;" : "=r"(rm[1]) : "r"(m1), "r"(d));
    }

    float c = 0.0f;
    float u_next = (kq == 0) ? __ldg(&g_G2[gr]) : 0.0f;
    int ph0 = 0, ph1 = 0;
    int wid = tid >> 5, lane = tid & 31;

    for (int r = 0; r < TB; r++) {
        int buf = r & 1;
        if (r > 0) {
            if (wid < 8) {
                if (lane == 0) {
                    uint32_t bar = mbb + (uint32_t)(buf * 8 + wid) * 8u;
                    mbar_wait_cluster(bar, (uint32_t)(buf ? ph1 : ph0));
                }
                __syncwarp();
            }
            if (buf) ph1 ^= 1; else ph0 ^= 1;
        }
        __syncthreads();   // join waiters; publishes acquired h to whole CTA

        float u = u_next;
        if (kq == 0 && r + 1 < TB) u_next = __ldg(&g_G2[(size_t)(r + 1) * G2N + gr]);

        const ulonglong2* hp = (const ulonglong2*)(&sh_h[buf][kq * 64]);
        unsigned long long acc01 = 0ull, acc23 = 0ull;
#pragma unroll
        for (int i = 0; i < 16; i++) {
            ulonglong2 hv = hp[i];
            asm("fma.rn.f32x2 %0, %1, %2, %3;" : "=l"(acc01) : "l"(w2[2 * i]), "l"(hv.x), "l"(acc01));
            asm("fma.rn.f32x2 %0, %1, %2, %3;" : "=l"(acc23) : "l"(w2[2 * i + 1]), "l"(hv.y), "l"(acc23));
        }
        float acc = (__uint_as_float((unsigned)acc01) + __uint_as_float((unsigned)(acc01 >> 32)))
                  + (__uint_as_float((unsigned)acc23) + __uint_as_float((unsigned)(acc23 >> 32)));
        acc += __shfl_xor_sync(0xffffffffu, acc, 1);
        acc += __shfl_xor_sync(0xffffffffu, acc, 2);

        if (kq == 0) {
            float pre = acc + u;
            sg2[lr] = (g == 2) ? tanhf(pre) : sigf(pre);
        }
        __syncthreads();   // sg2 ready; orders all reads of sh_h[buf] before release below

        int nb = buf ^ 1;
        if (tid < 32) {
            float gi = sg2[tid];
            float gf = sg2[32 + tid];
            float gc = sg2[64 + tid];
            float go = sg2[96 + tid];
            c = fmaf(gf, c, gi * gc);
            float h = go * tanhf(c);
            sh_h[nb][(int)rank * 32 + tid] = h;     // local stage
            __syncwarp();
            int q = tid & 3;
            const float4* sp = (const float4*)(&sh_h[nb][(int)rank * 32 + q * 8]);
            float4 v0 = sp[0], v1 = sp[1];
            uint32_t dst = rh[nb];
            asm volatile("st.shared::cluster.v4.f32 [%0], {%1,%2,%3,%4};"
                         :: "r"(dst), "f"(v0.x), "f"(v0.y), "f"(v0.z), "f"(v0.w) : "memory");
            asm volatile("st.shared::cluster.v4.f32 [%0], {%1,%2,%3,%4};"
                         :: "r"(dst + 16u), "f"(v1.x), "f"(v1.y), "f"(v1.z), "f"(v1.w) : "memory");
            asm volatile("mbarrier.arrive.release.cluster.shared::cluster.b64 _, [%0];"
                         :: "r"(rm[nb]) : "memory");
        }
    }

    // final h lives in buffer 0 (written at step TB-1); wait for last arrivals
    if (wid < 8) {
        if (lane == 0) {
            uint32_t bar = mbb + (uint32_t)(0 * 8 + wid) * 8u;
            mbar_wait_cluster(bar, (uint32_t)ph0);
        }
        __syncwarp();
    }
    __syncthreads();
    if (rank == 0 && tid < H2) g_hT2[tid] = sh_h[0][tid];

    asm volatile("barrier.cluster.arrive.aligned;" ::: "memory");
    asm volatile("barrier.cluster.wait.aligned;" ::: "memory");
}

// ---------------- tail MLP ----------------
__global__ void mlp_kernel(const float* __restrict__ W1, const float* __restrict__ b1,
                           const float* __restrict__ W2, const float* __restrict__ b2,
                           float* __restrict__ out) {
    __shared__ float emb[H2];
    __shared__ float o1[128];
    int tid = threadIdx.x;  // 128
    {
        float h0 = g_hT2[tid];
        float h1 = g_hT2[tid + 128];
        emb[tid]       = h0 + h0 * h0;
        emb[tid + 128] = h1 + h1 * h1;
    }
    __syncthreads();
    float s = b1[tid];
    const float* wrow = W1 + (size_t)tid * H2;
#pragma unroll 8
    for (int k = 0; k < H2; k++) s = fmaf(emb[k], wrow[k], s);
    o1[tid] = s;
    __syncthreads();
    if (tid < 10) {
        float s2 = b2[tid];
        const float* w2r = W2 + (size_t)tid * 128;
#pragma unroll 8
        for (int k = 0; k < 128; k++) s2 = fmaf(o1[k], w2r[k], s2);
        out[tid] = s2;
    }
}

extern "C" void kernel_launch(void* const* d_in, const int* in_sizes, int n_in,
                              void* d_out, int out_size) {
    const float* x     = (const float*)d_in[0];
    const float* W_ih1 = (const float*)d_in[1];
    const float* W_hh1 = (const float*)d_in[2];
    const float* b_ih1 = (const float*)d_in[3];
    const float* b_hh1 = (const float*)d_in[4];
    const float* W_ih2 = (const float*)d_in[5];
    const float* W_hh2 = (const float*)d_in[6];
    const float* b_ih2 = (const float*)d_in[7];
    const float* b_hh2 = (const float*)d_in[8];
    const float* W1    = (const float*)d_in[9];
    const float* b1    = (const float*)d_in[10];
    const float* W2    = (const float*)d_in[11];
    const float* b2    = (const float*)d_in[12];
    float* out = (float*)d_out;

    zero_state<<<128, 256>>>();

    gemm64<0><<<dim3(G1N / 64, TB / 64), 256>>>(x, W_ih1, b_ih1, b_hh1);

    for (int t = 0; t < TSTEPS; t++) {
        lstm1_step<<<128, 512>>>(W_hh1, t);
    }

    gemm64<1><<<dim3(G2N / 64, TB / 64), 256>>>(x, W_ih2, b_ih2, b_hh2);

    lstm2_kernel<<<8, 512>>>(W_hh2);

    mlp_kernel<<<1, 128>>>(W1, b1, W2, b2, out);
}